// round 1
// baseline (speedup 1.0000x reference)
#include <cuda_runtime.h>
#include <math.h>
#include <stdint.h>

// ---------------------------------------------------------------------------
// RetinaHead focal + smooth-L1 loss.
//   clas    [B,A,C]  f32
//   regs    [B,A,4]  f32
//   anchors [1,A,4]  f32 (corner form)
//   targets [B,T,5]  f32 (x1,y1,x2,y2,label)   label==-1 -> padded/invalid
// out: [2] f32 = (mean_b cls_loss_b, mean_b reg_loss_b)
// ---------------------------------------------------------------------------

#define MAX_B 64
#define TILE  256   // anchors per block == threads per block

__device__ double g_cls[MAX_B];
__device__ double g_reg[MAX_B];
__device__ int    g_npos[MAX_B];

__global__ void rhl_zero_kernel() {
    int i = threadIdx.x;
    if (i < MAX_B) { g_cls[i] = 0.0; g_reg[i] = 0.0; g_npos[i] = 0; }
}

__global__ __launch_bounds__(TILE)
void rhl_main_kernel(const float* __restrict__ clas,
                     const float* __restrict__ regs,
                     const float* __restrict__ anchors,
                     const float* __restrict__ targets,
                     int A, int C, int T)
{
    extern __shared__ float smem[];          // [T*5] targets, then [TILE] int codes
    float* st     = smem;
    int*   s_code = (int*)(smem + (size_t)T * 5);

    __shared__ double s_c[8];
    __shared__ float  s_r[8];
    __shared__ int    s_n[8];

    const int tid = threadIdx.x;
    const int b   = blockIdx.y;
    const int a0  = blockIdx.x * TILE;

    // ---- load this image's targets into smem ----
    for (int i = tid; i < T * 5; i += TILE)
        st[i] = targets[(size_t)b * T * 5 + i];
    __syncthreads();

    // ================= phase 1: per-anchor assignment ======================
    // code: >=0 -> positive, value = matched class
    //       -2  -> negative (iou_max < 0.4)
    //       -1  -> ignore   (0.4 <= iou_max < 0.5)
    float regloss = 0.0f;
    int   npos    = 0;
    int   code    = -1;

    const int a = a0 + tid;
    if (a < A) {
        const float4 ab = ((const float4*)anchors)[a];
        const float ax1 = ab.x, ay1 = ab.y, ax2 = ab.z, ay2 = ab.w;
        const float areaA = __fmul_rn(ax2 - ax1, ay2 - ay1);

        float best = -1.0f;
        int   bestt = 0;
        for (int t = 0; t < T; ++t) {
            const float tx1 = st[t*5+0], ty1 = st[t*5+1];
            const float tx2 = st[t*5+2], ty2 = st[t*5+3];
            const float lab = st[t*5+4];
            const float lx = fmaxf(ax1, tx1), ly = fmaxf(ay1, ty1);
            const float rx = fminf(ax2, tx2), ry = fminf(ay2, ty2);
            const float w = fmaxf(rx - lx, 0.0f), h = fmaxf(ry - ly, 0.0f);
            const float inter = __fmul_rn(w, h);
            const float areaT = __fmul_rn(tx2 - tx1, ty2 - ty1);
            // match XLA op order exactly: (areaA + areaT) - inter, IEEE divide
            float iou = inter / ((areaA + areaT) - inter);
            if (lab == -1.0f) iou = -1.0f;
            if (iou > best) { best = iou; bestt = t; }   // first-max argmax
        }

        if (best >= 0.5f) {
            code = (int)st[bestt*5+4];
            npos = 1;
            // ---- smooth-L1 on encoded box ----
            const float tx1 = st[bestt*5+0], ty1 = st[bestt*5+1];
            const float tx2 = st[bestt*5+2], ty2 = st[bestt*5+3];
            const float pcx = (ax1 + ax2) * 0.5f, pcy = (ay1 + ay2) * 0.5f;
            const float pw  = ax2 - ax1,          ph  = ay2 - ay1;
            const float g0 = ((tx1 + tx2) * 0.5f - pcx) / (0.1f * pw);
            const float g1 = ((ty1 + ty2) * 0.5f - pcy) / (0.1f * ph);
            const float g2 = logf((tx2 - tx1) / pw) / 0.2f;
            const float g3 = logf((ty2 - ty1) / ph) / 0.2f;
            const float4 rg = ((const float4*)regs)[(size_t)b * A + a];
            const float ge[4] = {g0, g1, g2, g3};
            const float rr[4] = {rg.x, rg.y, rg.z, rg.w};
            #pragma unroll
            for (int k = 0; k < 4; ++k) {
                const float d = fabsf(ge[k] - rr[k]);
                regloss += (d <= (1.0f/9.0f)) ? (4.5f * d) * d
                                              : d - (0.5f/9.0f);
            }
        } else if (best < 0.4f) {
            code = -2;
        } else {
            code = -1;
        }
    }
    s_code[tid] = code;
    __syncthreads();

    // ================= phase 2: focal loss over tile's class scores ========
    const int tileA = min(TILE, A - a0);
    float acc = 0.0f;

    if ((C & 3) == 0) {
        const float4* cp4 = (const float4*)(clas + ((size_t)b * A + a0) * C);
        const int n4 = tileA * C / 4;
        // incremental anchor/class-index tracking (avoid per-iter idiv)
        const int stepEl = TILE * 4;
        const int q = stepEl / C, r = stepEl % C;
        int el = tid * 4;
        int al = el / C;
        int cl = el - al * C;
        for (int i = tid; i < n4; i += TILE) {
            const int ac = s_code[al];
            const float4 v = cp4[i];
            const float vv[4] = {v.x, v.y, v.z, v.w};
            #pragma unroll
            for (int k = 0; k < 4; ++k) {
                const float c  = fminf(fmaxf(vv[k], 1e-4f), 1.0f - 1e-4f);
                const float om = 1.0f - c;
                const bool one = (ac == cl + k);   // ac>=0 && matched class
                const float lg = __logf(one ? c : om);
                const float w  = one ? 0.25f * om * om : 0.75f * c * c;
                acc += (ac == -1) ? 0.0f : -w * lg;
            }
            al += q; cl += r;
            if (cl >= C) { cl -= C; ++al; }
        }
    } else {
        const float* cp = clas + ((size_t)b * A + a0) * C;
        const int n = tileA * C;
        for (int i = tid; i < n; i += TILE) {
            const int al = i / C, clc = i - al * C;
            const int ac = s_code[al];
            const float c  = fminf(fmaxf(cp[i], 1e-4f), 1.0f - 1e-4f);
            const float om = 1.0f - c;
            const bool one = (ac == clc);
            const float lg = __logf(one ? c : om);
            const float w  = one ? 0.25f * om * om : 0.75f * c * c;
            acc += (ac == -1) ? 0.0f : -w * lg;
        }
    }

    // ================= block reduction + global accumulate =================
    float cs = acc, rs = regloss;
    int   ns = npos;
    #pragma unroll
    for (int o = 16; o; o >>= 1) {
        cs += __shfl_down_sync(0xffffffffu, cs, o);
        rs += __shfl_down_sync(0xffffffffu, rs, o);
        ns += __shfl_down_sync(0xffffffffu, ns, o);
    }
    const int wid = tid >> 5, lane = tid & 31;
    if (lane == 0) { s_c[wid] = (double)cs; s_r[wid] = rs; s_n[wid] = ns; }
    __syncthreads();
    if (tid == 0) {
        double tc = 0.0; float tr = 0.0f; int tn = 0;
        const int nw = (TILE + 31) / 32;
        for (int w = 0; w < nw; ++w) { tc += s_c[w]; tr += s_r[w]; tn += s_n[w]; }
        atomicAdd(&g_cls[b], tc);
        atomicAdd(&g_reg[b], (double)tr);
        atomicAdd(&g_npos[b], tn);
    }
}

__global__ void rhl_final_kernel(const float* __restrict__ targets,
                                 float* __restrict__ out, int B, int T)
{
    if (threadIdx.x != 0 || blockIdx.x != 0) return;
    double cs = 0.0, rs = 0.0;
    for (int b = 0; b < B; ++b) {
        bool hv = false;
        for (int t = 0; t < T; ++t)
            if (targets[((size_t)b * T + t) * 5 + 4] != -1.0f) { hv = true; break; }
        const int np = g_npos[b];
        const double npd = (double)np;
        const double cl = hv ? g_cls[b] / fmax(npd, 1.0) : 0.0;
        const double rl = (hv && np > 0) ? g_reg[b] / (npd * 4.0) : 0.0;
        cs += cl; rs += rl;
    }
    out[0] = (float)(cs / (double)B);
    out[1] = (float)(rs / (double)B);
}

extern "C" void kernel_launch(void* const* d_in, const int* in_sizes, int n_in,
                              void* d_out, int out_size)
{
    const float* clas    = (const float*)d_in[0];
    const float* regs    = (const float*)d_in[1];
    const float* anchors = (const float*)d_in[2];
    const float* targets = (const float*)d_in[3];
    float* out = (float*)d_out;

    const int A = in_sizes[2] / 4;                 // anchors [1,A,4]
    const int B = in_sizes[1] / (A * 4);           // regs [B,A,4]
    const int C = in_sizes[0] / (B * A);           // clas [B,A,C]
    const int T = in_sizes[3] / (B * 5);           // targets [B,T,5]

    rhl_zero_kernel<<<1, MAX_B>>>();

    dim3 grid((A + TILE - 1) / TILE, B);
    const size_t smem = (size_t)T * 5 * sizeof(float) + TILE * sizeof(int);
    rhl_main_kernel<<<grid, TILE, smem>>>(clas, regs, anchors, targets, A, C, T);

    rhl_final_kernel<<<1, 32>>>(targets, out, B, T);
}

// round 2
// speedup vs baseline: 1.0902x; 1.0902x over previous
#include <cuda_runtime.h>
#include <math.h>
#include <stdint.h>

// ---------------------------------------------------------------------------
// RetinaHead focal + smooth-L1 loss.
//   clas    [B,A,C]  f32
//   regs    [B,A,4]  f32
//   anchors [1,A,4]  f32 (corner form)
//   targets [B,T,5]  f32 (x1,y1,x2,y2,label)   label==-1 -> padded/invalid
// out: [2] f32 = (mean_b cls_loss_b, mean_b reg_loss_b)
// ---------------------------------------------------------------------------

#define MAX_B 64
#define TILE  256   // anchors per block == threads per block

__device__ double g_cls[MAX_B];   // zero-initialized at module load;
__device__ double g_reg[MAX_B];   // final kernel resets them after use so
__device__ int    g_npos[MAX_B];  // every graph replay starts from zero.

// focal loss for one float4 of class scores of one anchor
//   ac : anchor code (>=0 pos class, -2 negative, -1 ignore)
//   cl : class index of v.x
__device__ __forceinline__ float focal4(float4 v, int ac, int cl)
{
    const float LN2  = 0.6931471805599453f;
    const float A1   = 0.25f * LN2;   // alpha for the "one" entry
    const float A0   = 0.75f * LN2;   // alpha for the "zero" entries
    float r = 0.0f;
    const float vv[4] = {v.x, v.y, v.z, v.w};
    const float a0m = (ac == -1) ? 0.0f : A0;  // ignore-mask folded into alpha
    const float a1m = (ac == -1) ? 0.0f : A1;
    #pragma unroll
    for (int k = 0; k < 4; ++k) {
        const float c    = fminf(fmaxf(vv[k], 1e-4f), 1.0f - 1e-4f);
        const float om   = 1.0f - c;
        const bool  one  = (ac == cl + k);
        const float s    = one ? om : c;      // squared focal factor
        const float larg = one ? c  : om;     // log argument
        const float lg2  = __log2f(larg);     // <= 0
        const float af   = one ? a1m : a0m;
        const float p    = af * s * s;
        r = fmaf(-p, lg2, r);                 // += af * s^2 * (-ln2*log2) = w*(-ln larg)
    }
    return r;
}

template<int C_FIXED>
__global__ __launch_bounds__(TILE)
void rhl_main_kernel(const float* __restrict__ clas,
                     const float* __restrict__ regs,
                     const float* __restrict__ anchors,
                     const float* __restrict__ targets,
                     int A, int C_rt, int T)
{
    const int C = (C_FIXED > 0) ? C_FIXED : C_rt;

    extern __shared__ char smem_raw[];
    float4* s_box  = (float4*)smem_raw;                                  // [T]
    float2* s_meta = (float2*)(smem_raw + sizeof(float4) * (size_t)T);   // [T] (label, area)
    int*    s_code = (int*)(smem_raw + (sizeof(float4)+sizeof(float2)) * (size_t)T);

    __shared__ double s_c[TILE / 32];
    __shared__ float  s_r[TILE / 32];
    __shared__ int    s_n[TILE / 32];

    const int tid = threadIdx.x;
    const int b   = blockIdx.y;
    const int a0  = blockIdx.x * TILE;

    // ---- load & pack this image's targets ----
    for (int t = tid; t < T; t += TILE) {
        const float* tp = targets + ((size_t)b * T + t) * 5;
        const float x1 = tp[0], y1 = tp[1], x2 = tp[2], y2 = tp[3], lb = tp[4];
        s_box[t]  = make_float4(x1, y1, x2, y2);
        s_meta[t] = make_float2(lb, __fmul_rn(x2 - x1, y2 - y1));
    }
    __syncthreads();

    // ================= phase 1: per-anchor assignment ======================
    float regloss = 0.0f;
    int   npos    = 0;
    int   code    = -1;   // -2 negative, -1 ignore, >=0 positive class

    const int a = a0 + tid;
    if (a < A) {
        const float4 ab = ((const float4*)anchors)[a];
        const float ax1 = ab.x, ay1 = ab.y, ax2 = ab.z, ay2 = ab.w;
        const float areaA = __fmul_rn(ax2 - ax1, ay2 - ay1);

        float best = -1.0f;
        int   bestt = 0;
        for (int t = 0; t < T; ++t) {
            const float4 tb = s_box[t];
            const float2 tm = s_meta[t];
            const float lx = fmaxf(ax1, tb.x), ly = fmaxf(ay1, tb.y);
            const float rx = fminf(ax2, tb.z), ry = fminf(ay2, tb.w);
            const float w = fmaxf(rx - lx, 0.0f), h = fmaxf(ry - ly, 0.0f);
            const float inter = __fmul_rn(w, h);
            // XLA op order: (area_a + area_b) - inter
            float iou = inter / ((areaA + tm.y) - inter);
            if (tm.x == -1.0f) iou = -1.0f;
            if (iou > best) { best = iou; bestt = t; }   // first-max argmax
        }

        if (best >= 0.5f) {
            code = (int)s_meta[bestt].x;
            npos = 1;
            const float4 tb = s_box[bestt];
            const float pcx = (ax1 + ax2) * 0.5f, pcy = (ay1 + ay2) * 0.5f;
            const float pw  = ax2 - ax1,          ph  = ay2 - ay1;
            const float g0 = ((tb.x + tb.z) * 0.5f - pcx) / (0.1f * pw);
            const float g1 = ((tb.y + tb.w) * 0.5f - pcy) / (0.1f * ph);
            const float g2 = logf((tb.z - tb.x) / pw) / 0.2f;
            const float g3 = logf((tb.w - tb.y) / ph) / 0.2f;
            const float4 rg = ((const float4*)regs)[(size_t)b * A + a];
            const float ge[4] = {g0, g1, g2, g3};
            const float rr[4] = {rg.x, rg.y, rg.z, rg.w};
            #pragma unroll
            for (int k = 0; k < 4; ++k) {
                const float d = fabsf(ge[k] - rr[k]);
                regloss += (d <= (1.0f/9.0f)) ? (4.5f * d) * d
                                              : d - (0.5f/9.0f);
            }
        } else if (best < 0.4f) {
            code = -2;
        }
    }
    s_code[tid] = code;
    __syncthreads();

    // ================= phase 2: focal loss over tile's class scores ========
    const int tileA = min(TILE, A - a0);
    float acc = 0.0f;

    if ((C & 3) == 0) {
        const int q = C / 4;                               // float4s per anchor
        const float4* __restrict__ cp4 =
            (const float4*)(clas + ((size_t)b * A + a0) * C);
        const int n4 = tileA * q;
        int i = tid;
        // 4x-unrolled: 4 independent streaming loads per iteration (MLP=4)
        for (; i + 3 * TILE < n4; i += 4 * TILE) {
            const float4 v0 = __ldcs(cp4 + i);
            const float4 v1 = __ldcs(cp4 + i + TILE);
            const float4 v2 = __ldcs(cp4 + i + 2 * TILE);
            const float4 v3 = __ldcs(cp4 + i + 3 * TILE);
            const int i0 = i, i1 = i + TILE, i2 = i + 2 * TILE, i3 = i + 3 * TILE;
            const int al0 = i0 / q, al1 = i1 / q, al2 = i2 / q, al3 = i3 / q;
            acc += focal4(v0, s_code[al0], (i0 - al0 * q) * 4);
            acc += focal4(v1, s_code[al1], (i1 - al1 * q) * 4);
            acc += focal4(v2, s_code[al2], (i2 - al2 * q) * 4);
            acc += focal4(v3, s_code[al3], (i3 - al3 * q) * 4);
        }
        for (; i < n4; i += TILE) {
            const int al = i / q;
            acc += focal4(__ldcs(cp4 + i), s_code[al], (i - al * q) * 4);
        }
    } else {
        const float* cp = clas + ((size_t)b * A + a0) * C;
        const int n = tileA * C;
        const float LN2 = 0.6931471805599453f;
        for (int i = tid; i < n; i += TILE) {
            const int al = i / C, clc = i - al * C;
            const int ac = s_code[al];
            const float c  = fminf(fmaxf(cp[i], 1e-4f), 1.0f - 1e-4f);
            const float om = 1.0f - c;
            const bool one = (ac == clc);
            const float s    = one ? om : c;
            const float larg = one ? c  : om;
            const float lg2  = __log2f(larg);
            float af = one ? 0.25f * LN2 : 0.75f * LN2;
            if (ac == -1) af = 0.0f;
            acc = fmaf(-(af * s * s), lg2, acc);
        }
    }

    // ================= block reduction + global accumulate =================
    float cs = acc, rs = regloss;
    int   ns = npos;
    #pragma unroll
    for (int o = 16; o; o >>= 1) {
        cs += __shfl_down_sync(0xffffffffu, cs, o);
        rs += __shfl_down_sync(0xffffffffu, rs, o);
        ns += __shfl_down_sync(0xffffffffu, ns, o);
    }
    const int wid = tid >> 5, lane = tid & 31;
    if (lane == 0) { s_c[wid] = (double)cs; s_r[wid] = rs; s_n[wid] = ns; }
    __syncthreads();
    if (tid == 0) {
        double tc = 0.0; float tr = 0.0f; int tn = 0;
        #pragma unroll
        for (int w = 0; w < TILE / 32; ++w) { tc += s_c[w]; tr += s_r[w]; tn += s_n[w]; }
        atomicAdd(&g_cls[b], tc);
        atomicAdd(&g_reg[b], (double)tr);
        atomicAdd(&g_npos[b], tn);
    }
}

__global__ void rhl_final_kernel(const float* __restrict__ targets,
                                 float* __restrict__ out, int B, int T)
{
    if (threadIdx.x != 0 || blockIdx.x != 0) return;
    double cs = 0.0, rs = 0.0;
    for (int b = 0; b < B; ++b) {
        bool hv = false;
        for (int t = 0; t < T; ++t)
            if (targets[((size_t)b * T + t) * 5 + 4] != -1.0f) { hv = true; break; }
        const int np = g_npos[b];
        const double npd = (double)np;
        const double cl = hv ? g_cls[b] / fmax(npd, 1.0) : 0.0;
        const double rl = (hv && np > 0) ? g_reg[b] / (npd * 4.0) : 0.0;
        cs += cl; rs += rl;
    }
    out[0] = (float)(cs / (double)B);
    out[1] = (float)(rs / (double)B);
    // reset accumulators so the next graph replay starts from zero
    for (int i = 0; i < MAX_B; ++i) { g_cls[i] = 0.0; g_reg[i] = 0.0; g_npos[i] = 0; }
}

extern "C" void kernel_launch(void* const* d_in, const int* in_sizes, int n_in,
                              void* d_out, int out_size)
{
    const float* clas    = (const float*)d_in[0];
    const float* regs    = (const float*)d_in[1];
    const float* anchors = (const float*)d_in[2];
    const float* targets = (const float*)d_in[3];
    float* out = (float*)d_out;

    const int A = in_sizes[2] / 4;                 // anchors [1,A,4]
    const int B = in_sizes[1] / (A * 4);           // regs [B,A,4]
    const int C = in_sizes[0] / (B * A);           // clas [B,A,C]
    const int T = in_sizes[3] / (B * 5);           // targets [B,T,5]

    dim3 grid((A + TILE - 1) / TILE, B);
    const size_t smem = (sizeof(float4) + sizeof(float2)) * (size_t)T
                      + (size_t)TILE * sizeof(int);

    if (C == 80) {
        rhl_main_kernel<80><<<grid, TILE, smem>>>(clas, regs, anchors, targets, A, C, T);
    } else {
        rhl_main_kernel<0><<<grid, TILE, smem>>>(clas, regs, anchors, targets, A, C, T);
    }
    rhl_final_kernel<<<1, 32>>>(targets, out, B, T);
}